// round 1
// baseline (speedup 1.0000x reference)
#include <cuda_runtime.h>
#include <cstdint>
#include <cstddef>

// Problem dims (fixed by reference)
#define S_LEN 4096
#define B_SZ  8
#define D_SZ  1024
#define M_TOT (B_SZ * S_LEN)      // 32768 rows for phase-1 GEMM
#define P2_CTAS 128
#define P2_THREADS 128

// ---------------------------------------------------------------------------
// Scratch (static __device__ arrays — no allocation at runtime)
// ---------------------------------------------------------------------------
__device__ float g_gate[(size_t)M_TOT * D_SZ];   // sigmoid(gate_inputs), layout [b*S+s][e]
__device__ float g_proj[(size_t)M_TOT * D_SZ];   // projected_inputs,      layout [b*S+s][e]
__device__ float g_state[2][B_SZ * D_SZ];        // ping-pong state buffers
__device__ unsigned g_barcnt;
__device__ unsigned g_bargen;

// ---------------------------------------------------------------------------
// Init kernel: zero state buffer 0 and barrier vars (runs before phase2 in
// stream order — also makes graph replays deterministic)
// ---------------------------------------------------------------------------
__global__ void init_kernel() {
    int tid = blockIdx.x * blockDim.x + threadIdx.x;
    if (tid == 0) { g_barcnt = 0u; g_bargen = 0u; }
    for (int i = tid; i < B_SZ * D_SZ; i += gridDim.x * blockDim.x) {
        g_state[0][i] = 0.0f;
        g_state[1][i] = 0.0f;
    }
}

// ---------------------------------------------------------------------------
// Phase 1: z = x @ W_in^T + b_in ; gates = sigmoid(z[:, :D]) ; proj = z[:, D:]
// Classic 128x128x8 fp32 SGEMM, 256 threads, 8x8 microtile.
// C[m][n] = sum_k X[m][k] * Win[n][k]   (both K-major -> "NT" gemm)
// ---------------------------------------------------------------------------
__global__ __launch_bounds__(256, 2) void phase1_gemm(
    const float* __restrict__ X,
    const float* __restrict__ Win,
    const float* __restrict__ bin)
{
    __shared__ float As[8][128];
    __shared__ float Bs[8][128];

    const int bx = blockIdx.x;          // N tile: 0..15  (n0 = bx*128)
    const int by = blockIdx.y;          // M tile: 0..255 (m0 = by*128)
    const int tid = threadIdx.x;
    const int tx = tid & 15;            // 0..15
    const int ty = tid >> 4;            // 0..15
    const int m0 = by * 128;
    const int n0 = bx * 128;

    // loader mapping: each thread loads one float4 of A and one of B per K-tile
    const int lm = tid >> 1;            // row within tile 0..127
    const int lk = (tid & 1) * 4;       // k offset 0 or 4

    float acc[8][8];
    #pragma unroll
    for (int i = 0; i < 8; ++i)
        #pragma unroll
        for (int j = 0; j < 8; ++j) acc[i][j] = 0.0f;

    const float* Aptr = X   + (size_t)(m0 + lm) * D_SZ + lk;
    const float* Bptr = Win + (size_t)(n0 + lm) * D_SZ + lk;

    for (int k0 = 0; k0 < D_SZ; k0 += 8) {
        float4 a = *(const float4*)(Aptr + k0);
        float4 b = *(const float4*)(Bptr + k0);
        As[lk + 0][lm] = a.x; As[lk + 1][lm] = a.y;
        As[lk + 2][lm] = a.z; As[lk + 3][lm] = a.w;
        Bs[lk + 0][lm] = b.x; Bs[lk + 1][lm] = b.y;
        Bs[lk + 2][lm] = b.z; Bs[lk + 3][lm] = b.w;
        __syncthreads();

        #pragma unroll
        for (int k = 0; k < 8; ++k) {
            float ra[8], rb[8];
            #pragma unroll
            for (int i = 0; i < 8; ++i) ra[i] = As[k][ty * 8 + i];
            #pragma unroll
            for (int j = 0; j < 8; ++j) rb[j] = Bs[k][tx * 8 + j];
            #pragma unroll
            for (int i = 0; i < 8; ++i)
                #pragma unroll
                for (int j = 0; j < 8; ++j)
                    acc[i][j] += ra[i] * rb[j];
        }
        __syncthreads();
    }

    // epilogue: bias, sigmoid split. Each CTA lies entirely in gate half
    // (bx < 8) or proj half (bx >= 8) since 1024 is a multiple of 128.
    const bool is_gate = (n0 < D_SZ);
    #pragma unroll
    for (int i = 0; i < 8; ++i) {
        const int m = m0 + ty * 8 + i;
        #pragma unroll
        for (int j = 0; j < 8; ++j) {
            const int n = n0 + tx * 8 + j;
            float v = acc[i][j] + bin[n];
            if (is_gate) {
                g_gate[(size_t)m * D_SZ + n] = 1.0f / (1.0f + expf(-v));
            } else {
                g_proj[(size_t)m * D_SZ + (n - D_SZ)] = v;
            }
        }
    }
}

// ---------------------------------------------------------------------------
// Grid-wide barrier (persistent kernel, 128 CTAs, all co-resident)
// ---------------------------------------------------------------------------
__device__ __forceinline__ void grid_barrier(unsigned target) {
    __syncthreads();                       // all block work done, smem reads done
    if (threadIdx.x == 0) {
        __threadfence();                   // publish my global writes
        unsigned ticket = atomicAdd(&g_barcnt, 1u);
        if (ticket == target * P2_CTAS - 1u) {
            atomicExch(&g_bargen, target); // release
        } else {
            while (*((volatile unsigned*)&g_bargen) < target) {
                __nanosleep(40);
            }
        }
        __threadfence();                   // acquire
    }
    __syncthreads();
}

// ---------------------------------------------------------------------------
// Phase 2: sequential gated recurrence, 4096 steps.
// 128 CTAs x 128 threads. CTA c owns output columns e in [8c, 8c+8).
// Warp g (0..3) owns columns {8c+2g, 8c+2g+1}, K split across 32 lanes
// (lane covers d = 4*lane + 128*kk, kk=0..7, as float4). W_s rows live in
// registers for the whole kernel. Full state staged to SMEM each step.
// ---------------------------------------------------------------------------
__global__ __launch_bounds__(P2_THREADS, 1) void phase2_scan(
    const float* __restrict__ Ws,
    const float* __restrict__ bs,
    float* __restrict__ out)
{
    __shared__ float4 st4[B_SZ * (D_SZ / 4)];   // 2048 float4 = 32 KB

    const int tid  = threadIdx.x;
    const int lane = tid & 31;
    const int grp  = tid >> 5;                  // warp id 0..3
    const int e0   = blockIdx.x * 8 + grp * 2;  // first of this warp's 2 columns

    // W_s rows in registers: W0/W1[kk] = float4 of row e0 / e0+1 at d = 4*(lane+32kk)
    float4 W0[8], W1[8];
    #pragma unroll
    for (int kk = 0; kk < 8; ++kk) {
        W0[kk] = *(const float4*)&Ws[(size_t)e0       * D_SZ + 4 * (lane + 32 * kk)];
        W1[kk] = *(const float4*)&Ws[(size_t)(e0 + 1) * D_SZ + 4 * (lane + 32 * kk)];
    }

    // epilogue lane assignment: lanes 0..15 each own one (batch, column) pair
    const int mb = lane >> 1;                   // batch 0..7
    const int mj = lane & 1;                    // which of the 2 columns
    const int me = e0 + mj;
    const float bsv = (lane < 16) ? bs[me] : 0.0f;

    for (int t = 0; t < S_LEN; ++t) {
        const float4* cur = (const float4*)g_state[t & 1];

        // prefetch gate / proj for this step (independent of state)
        float gv = 0.0f, pv = 0.0f;
        if (lane < 16) {
            size_t gi = ((size_t)mb * S_LEN + t) * D_SZ + me;
            gv = g_gate[gi];
            pv = g_proj[gi];
        }

        // stage full state into SMEM (32 KB, coalesced float4)
        #pragma unroll
        for (int i = 0; i < 16; ++i)
            st4[tid + P2_THREADS * i] = cur[tid + P2_THREADS * i];
        __syncthreads();

        // partial dots: acc[b][j] over this lane's 32 d-values
        float acc[8][2];
        #pragma unroll
        for (int b = 0; b < 8; ++b) { acc[b][0] = 0.0f; acc[b][1] = 0.0f; }

        #pragma unroll
        for (int b = 0; b < 8; ++b) {
            #pragma unroll
            for (int kk = 0; kk < 8; ++kk) {
                float4 s = st4[b * 256 + lane + 32 * kk];
                acc[b][0] += s.x * W0[kk].x + s.y * W0[kk].y
                           + s.z * W0[kk].z + s.w * W0[kk].w;
                acc[b][1] += s.x * W1[kk].x + s.y * W1[kk].y
                           + s.z * W1[kk].z + s.w * W1[kk].w;
            }
        }

        // butterfly reduce across the warp (every lane ends with full sums)
        #pragma unroll
        for (int b = 0; b < 8; ++b) {
            #pragma unroll
            for (int j = 0; j < 2; ++j) {
                float v = acc[b][j];
                #pragma unroll
                for (int m = 16; m > 0; m >>= 1)
                    v += __shfl_xor_sync(0xffffffffu, v, m);
                acc[b][j] = v;
            }
        }

        // epilogue: gated update, emit output, write next-state slice
        if (lane < 16) {
            float mix  = acc[mb][mj] + bsv + pv;
            float sold = ((const float*)st4)[mb * D_SZ + me];
            float nxt  = gv * mix + (1.0f - gv) * sold;
            out[((size_t)mb * S_LEN + t) * D_SZ + me] = nxt;
            g_state[(t + 1) & 1][mb * D_SZ + me] = nxt;
        }

        grid_barrier((unsigned)(t + 1));
    }
}

// ---------------------------------------------------------------------------
// Launch
// Inputs (metadata order): x [B,S,D] f32, W_in [2D,D] f32, b_in [2D] f32,
//                          W_s [D,D] f32, b_s [D] f32. Output: [B,S,D] f32.
// ---------------------------------------------------------------------------
extern "C" void kernel_launch(void* const* d_in, const int* in_sizes, int n_in,
                              void* d_out, int out_size) {
    const float* x    = (const float*)d_in[0];
    const float* W_in = (const float*)d_in[1];
    const float* b_in = (const float*)d_in[2];
    const float* W_s  = (const float*)d_in[3];
    const float* b_s  = (const float*)d_in[4];
    float* out = (float*)d_out;

    init_kernel<<<16, 512>>>();

    dim3 g1(16, 256);   // N tiles x M tiles
    phase1_gemm<<<g1, 256>>>(x, W_in, b_in);

    phase2_scan<<<P2_CTAS, P2_THREADS>>>(W_s, b_s, out);
}

// round 2
// speedup vs baseline: 1.0046x; 1.0046x over previous
#include <cuda_runtime.h>
#include <cstdint>
#include <cstddef>

// Problem dims (fixed by reference)
#define S_LEN 4096
#define B_SZ  8
#define D_SZ  1024
#define M_TOT (B_SZ * S_LEN)      // 32768 rows for phase-1 GEMM
#define P2_CTAS 128
#define P2_THREADS 128

// ---------------------------------------------------------------------------
// Scratch (static __device__ arrays — no allocation at runtime)
// ---------------------------------------------------------------------------
__device__ float g_gate[(size_t)M_TOT * D_SZ];   // sigmoid(gate_inputs), layout [b*S+s][e]
__device__ float g_proj[(size_t)M_TOT * D_SZ];   // projected_inputs,      layout [b*S+s][e]
__device__ float g_state[2][B_SZ * D_SZ];        // ping-pong state buffers
__device__ unsigned g_barcnt;
__device__ unsigned g_bargen;

// ---------------------------------------------------------------------------
// Init kernel: zero state buffer 0 and barrier vars (runs before phase2 in
// stream order — also makes graph replays deterministic)
// ---------------------------------------------------------------------------
__global__ void init_kernel() {
    int tid = blockIdx.x * blockDim.x + threadIdx.x;
    if (tid == 0) { g_barcnt = 0u; g_bargen = 0u; }
    for (int i = tid; i < B_SZ * D_SZ; i += gridDim.x * blockDim.x) {
        g_state[0][i] = 0.0f;
        g_state[1][i] = 0.0f;
    }
}

// ---------------------------------------------------------------------------
// Phase 1: z = x @ W_in^T + b_in ; gates = sigmoid(z[:, :D]) ; proj = z[:, D:]
// Classic 128x128x8 fp32 SGEMM, 256 threads, 8x8 microtile.
// C[m][n] = sum_k X[m][k] * Win[n][k]   (both K-major -> "NT" gemm)
// ---------------------------------------------------------------------------
__global__ __launch_bounds__(256, 2) void phase1_gemm(
    const float* __restrict__ X,
    const float* __restrict__ Win,
    const float* __restrict__ bin)
{
    __shared__ float As[8][128];
    __shared__ float Bs[8][128];

    const int bx = blockIdx.x;          // N tile: 0..15  (n0 = bx*128)
    const int by = blockIdx.y;          // M tile: 0..255 (m0 = by*128)
    const int tid = threadIdx.x;
    const int tx = tid & 15;            // 0..15
    const int ty = tid >> 4;            // 0..15
    const int m0 = by * 128;
    const int n0 = bx * 128;

    // loader mapping: each thread loads one float4 of A and one of B per K-tile
    const int lm = tid >> 1;            // row within tile 0..127
    const int lk = (tid & 1) * 4;       // k offset 0 or 4

    float acc[8][8];
    #pragma unroll
    for (int i = 0; i < 8; ++i)
        #pragma unroll
        for (int j = 0; j < 8; ++j) acc[i][j] = 0.0f;

    const float* Aptr = X   + (size_t)(m0 + lm) * D_SZ + lk;
    const float* Bptr = Win + (size_t)(n0 + lm) * D_SZ + lk;

    for (int k0 = 0; k0 < D_SZ; k0 += 8) {
        float4 a = *(const float4*)(Aptr + k0);
        float4 b = *(const float4*)(Bptr + k0);
        As[lk + 0][lm] = a.x; As[lk + 1][lm] = a.y;
        As[lk + 2][lm] = a.z; As[lk + 3][lm] = a.w;
        Bs[lk + 0][lm] = b.x; Bs[lk + 1][lm] = b.y;
        Bs[lk + 2][lm] = b.z; Bs[lk + 3][lm] = b.w;
        __syncthreads();

        #pragma unroll
        for (int k = 0; k < 8; ++k) {
            float ra[8], rb[8];
            #pragma unroll
            for (int i = 0; i < 8; ++i) ra[i] = As[k][ty * 8 + i];
            #pragma unroll
            for (int j = 0; j < 8; ++j) rb[j] = Bs[k][tx * 8 + j];
            #pragma unroll
            for (int i = 0; i < 8; ++i)
                #pragma unroll
                for (int j = 0; j < 8; ++j)
                    acc[i][j] += ra[i] * rb[j];
        }
        __syncthreads();
    }

    // epilogue: bias, sigmoid split. Each CTA lies entirely in gate half
    // (bx < 8) or proj half (bx >= 8) since 1024 is a multiple of 128.
    const bool is_gate = (n0 < D_SZ);
    #pragma unroll
    for (int i = 0; i < 8; ++i) {
        const int m = m0 + ty * 8 + i;
        #pragma unroll
        for (int j = 0; j < 8; ++j) {
            const int n = n0 + tx * 8 + j;
            float v = acc[i][j] + bin[n];
            if (is_gate) {
                g_gate[(size_t)m * D_SZ + n] = 1.0f / (1.0f + expf(-v));
            } else {
                g_proj[(size_t)m * D_SZ + (n - D_SZ)] = v;
            }
        }
    }
}

// ---------------------------------------------------------------------------
// Grid-wide barrier (persistent kernel, 128 CTAs, all co-resident)
// ---------------------------------------------------------------------------
__device__ __forceinline__ void grid_barrier(unsigned target) {
    __syncthreads();                       // all block work done, smem reads done
    if (threadIdx.x == 0) {
        __threadfence();                   // publish my global writes
        unsigned ticket = atomicAdd(&g_barcnt, 1u);
        if (ticket == target * P2_CTAS - 1u) {
            atomicExch(&g_bargen, target); // release
        } else {
            while (*((volatile unsigned*)&g_bargen) < target) {
                __nanosleep(40);
            }
        }
        __threadfence();                   // acquire
    }
    __syncthreads();
}

// ---------------------------------------------------------------------------
// Phase 2: sequential gated recurrence, 4096 steps.
// 128 CTAs x 128 threads. CTA c owns output columns e in [8c, 8c+8).
// Warp g (0..3) owns columns {8c+2g, 8c+2g+1}, K split across 32 lanes
// (lane covers d = 4*lane + 128*kk, kk=0..7, as float4). W_s rows live in
// registers for the whole kernel. Full state staged to SMEM each step.
// ---------------------------------------------------------------------------
__global__ __launch_bounds__(P2_THREADS, 1) void phase2_scan(
    const float* __restrict__ Ws,
    const float* __restrict__ bs,
    float* __restrict__ out)
{
    __shared__ float4 st4[B_SZ * (D_SZ / 4)];   // 2048 float4 = 32 KB

    const int tid  = threadIdx.x;
    const int lane = tid & 31;
    const int grp  = tid >> 5;                  // warp id 0..3
    const int e0   = blockIdx.x * 8 + grp * 2;  // first of this warp's 2 columns

    // W_s rows in registers: W0/W1[kk] = float4 of row e0 / e0+1 at d = 4*(lane+32kk)
    float4 W0[8], W1[8];
    #pragma unroll
    for (int kk = 0; kk < 8; ++kk) {
        W0[kk] = *(const float4*)&Ws[(size_t)e0       * D_SZ + 4 * (lane + 32 * kk)];
        W1[kk] = *(const float4*)&Ws[(size_t)(e0 + 1) * D_SZ + 4 * (lane + 32 * kk)];
    }

    // epilogue lane assignment: lanes 0..15 each own one (batch, column) pair
    const int mb = lane >> 1;                   // batch 0..7
    const int mj = lane & 1;                    // which of the 2 columns
    const int me = e0 + mj;
    const float bsv = (lane < 16) ? bs[me] : 0.0f;

    for (int t = 0; t < S_LEN; ++t) {
        const float4* cur = (const float4*)g_state[t & 1];

        // prefetch gate / proj for this step (independent of state)
        float gv = 0.0f, pv = 0.0f;
        if (lane < 16) {
            size_t gi = ((size_t)mb * S_LEN + t) * D_SZ + me;
            gv = g_gate[gi];
            pv = g_proj[gi];
        }

        // stage full state into SMEM (32 KB, coalesced float4)
        #pragma unroll
        for (int i = 0; i < 16; ++i)
            st4[tid + P2_THREADS * i] = cur[tid + P2_THREADS * i];
        __syncthreads();

        // partial dots: acc[b][j] over this lane's 32 d-values
        float acc[8][2];
        #pragma unroll
        for (int b = 0; b < 8; ++b) { acc[b][0] = 0.0f; acc[b][1] = 0.0f; }

        #pragma unroll
        for (int b = 0; b < 8; ++b) {
            #pragma unroll
            for (int kk = 0; kk < 8; ++kk) {
                float4 s = st4[b * 256 + lane + 32 * kk];
                acc[b][0] += s.x * W0[kk].x + s.y * W0[kk].y
                           + s.z * W0[kk].z + s.w * W0[kk].w;
                acc[b][1] += s.x * W1[kk].x + s.y * W1[kk].y
                           + s.z * W1[kk].z + s.w * W1[kk].w;
            }
        }

        // butterfly reduce across the warp (every lane ends with full sums)
        #pragma unroll
        for (int b = 0; b < 8; ++b) {
            #pragma unroll
            for (int j = 0; j < 2; ++j) {
                float v = acc[b][j];
                #pragma unroll
                for (int m = 16; m > 0; m >>= 1)
                    v += __shfl_xor_sync(0xffffffffu, v, m);
                acc[b][j] = v;
            }
        }

        // epilogue: gated update, emit output, write next-state slice
        if (lane < 16) {
            float mix  = acc[mb][mj] + bsv + pv;
            float sold = ((const float*)st4)[mb * D_SZ + me];
            float nxt  = gv * mix + (1.0f - gv) * sold;
            out[((size_t)mb * S_LEN + t) * D_SZ + me] = nxt;
            g_state[(t + 1) & 1][mb * D_SZ + me] = nxt;
        }

        grid_barrier((unsigned)(t + 1));
    }
}

// ---------------------------------------------------------------------------
// Launch
// Inputs (metadata order): x [B,S,D] f32, W_in [2D,D] f32, b_in [2D] f32,
//                          W_s [D,D] f32, b_s [D] f32. Output: [B,S,D] f32.
// ---------------------------------------------------------------------------
extern "C" void kernel_launch(void* const* d_in, const int* in_sizes, int n_in,
                              void* d_out, int out_size) {
    const float* x    = (const float*)d_in[0];
    const float* W_in = (const float*)d_in[1];
    const float* b_in = (const float*)d_in[2];
    const float* W_s  = (const float*)d_in[3];
    const float* b_s  = (const float*)d_in[4];
    float* out = (float*)d_out;

    init_kernel<<<16, 512>>>();

    dim3 g1(16, 256);   // N tiles x M tiles
    phase1_gemm<<<g1, 256>>>(x, W_in, b_in);

    phase2_scan<<<P2_CTAS, P2_THREADS>>>(W_s, b_s, out);
}

// round 3
// speedup vs baseline: 1.0616x; 1.0567x over previous
#include <cuda_runtime.h>
#include <cstdint>
#include <cstddef>

#define S_LEN 4096
#define B_SZ  8
#define D_SZ  1024
#define M_TOT (B_SZ * S_LEN)
#define P2_CTAS 128

__device__ float g_gate[(size_t)M_TOT * D_SZ];
__device__ float g_proj[(size_t)M_TOT * D_SZ];
__device__ float g_state[2][B_SZ * D_SZ];
__device__ unsigned g_barcnt;
__device__ unsigned g_bargen;

typedef unsigned long long u64;

__device__ __forceinline__ u64 ffma2(u64 a, u64 b, u64 c) {
    u64 d;
    asm("fma.rn.f32x2 %0, %1, %2, %3;" : "=l"(d) : "l"(a), "l"(b), "l"(c));
    return d;
}
__device__ __forceinline__ u64 packdup(float x) {
    u64 r;
    asm("mov.b64 %0, {%1, %1};" : "=l"(r) : "f"(x));
    return r;
}
__device__ __forceinline__ float2 u2f(u64 v) {
    float2 f;
    asm("mov.b64 {%0, %1}, %2;" : "=f"(f.x), "=f"(f.y) : "l"(v));
    return f;
}

// ---------------------------------------------------------------------------
// Phase 1: z = X@Win^T + bin; gate=sigmoid(z[:,:D]); proj=z[:,D:]
// 128x128x8 tile, 256 thr, 8x8 microtile via packed f32x2.
// CTA(0,0) also zeroes recurrence state + barrier (init merged here).
// ---------------------------------------------------------------------------
__global__ __launch_bounds__(256, 2) void phase1_gemm(
    const float* __restrict__ X, const float* __restrict__ Win,
    const float* __restrict__ bin)
{
    __shared__ float As[8][128];
    __shared__ float Bs[8][128];

    const int tid = threadIdx.x;
    const int tx = tid & 15, ty = tid >> 4;
    const int m0 = blockIdx.y * 128, n0 = blockIdx.x * 128;

    if (blockIdx.x == 0 && blockIdx.y == 0) {
        if (tid == 0) { g_barcnt = 0u; g_bargen = 0u; }
        for (int i = tid; i < B_SZ * D_SZ; i += 256) g_state[0][i] = 0.0f;
    }

    const int lm = tid >> 1;            // 0..127
    const int lk = (tid & 1) * 4;       // 0 or 4

    u64 acc[8][4];
    #pragma unroll
    for (int i = 0; i < 8; ++i)
        #pragma unroll
        for (int p = 0; p < 4; ++p) acc[i][p] = 0ull;

    const float* Aptr = X   + (size_t)(m0 + lm) * D_SZ + lk;
    const float* Bptr = Win + (size_t)(n0 + lm) * D_SZ + lk;

    for (int k0 = 0; k0 < D_SZ; k0 += 8) {
        float4 a = *(const float4*)(Aptr + k0);
        float4 b = *(const float4*)(Bptr + k0);
        As[lk + 0][lm] = a.x; As[lk + 1][lm] = a.y;
        As[lk + 2][lm] = a.z; As[lk + 3][lm] = a.w;
        Bs[lk + 0][lm] = b.x; Bs[lk + 1][lm] = b.y;
        Bs[lk + 2][lm] = b.z; Bs[lk + 3][lm] = b.w;
        __syncthreads();

        #pragma unroll
        for (int k = 0; k < 8; ++k) {
            float4 a0 = *(const float4*)&As[k][ty * 8];
            float4 a1 = *(const float4*)&As[k][ty * 8 + 4];
            u64 Ad[8] = {packdup(a0.x), packdup(a0.y), packdup(a0.z), packdup(a0.w),
                         packdup(a1.x), packdup(a1.y), packdup(a1.z), packdup(a1.w)};
            ulonglong2 b01 = *(const ulonglong2*)&Bs[k][tx * 8];
            ulonglong2 b23 = *(const ulonglong2*)&Bs[k][tx * 8 + 4];
            u64 Bp[4] = {b01.x, b01.y, b23.x, b23.y};
            #pragma unroll
            for (int i = 0; i < 8; ++i)
                #pragma unroll
                for (int p = 0; p < 4; ++p)
                    acc[i][p] = ffma2(Ad[i], Bp[p], acc[i][p]);
        }
        __syncthreads();
    }

    const bool is_gate = (n0 < D_SZ);
    #pragma unroll
    for (int i = 0; i < 8; ++i) {
        const int m = m0 + ty * 8 + i;
        #pragma unroll
        for (int p = 0; p < 4; ++p) {
            float2 f = u2f(acc[i][p]);
            const int n = n0 + tx * 8 + 2 * p;
            float v0 = f.x + bin[n];
            float v1 = f.y + bin[n + 1];
            if (is_gate) {
                g_gate[(size_t)m * D_SZ + n]     = 1.0f / (1.0f + __expf(-v0));
                g_gate[(size_t)m * D_SZ + n + 1] = 1.0f / (1.0f + __expf(-v1));
            } else {
                g_proj[(size_t)m * D_SZ + n - D_SZ]     = v0;
                g_proj[(size_t)m * D_SZ + n - D_SZ + 1] = v1;
            }
        }
    }
}

// ---------------------------------------------------------------------------
__device__ __forceinline__ void grid_barrier(unsigned target) {
    __syncthreads();
    if (threadIdx.x == 0) {
        __threadfence();
        unsigned ticket = atomicAdd(&g_barcnt, 1u);
        if (ticket == target * P2_CTAS - 1u) {
            atomicExch(&g_bargen, target);
        } else {
            while (*((volatile unsigned*)&g_bargen) < target) __nanosleep(32);
        }
        __threadfence();
    }
    __syncthreads();
}

// ---------------------------------------------------------------------------
// Phase 2: 4096-step recurrence. 128 CTAs x 128 thr.
// CTA owns cols [8blk, 8blk+8). Warp w: col-group cg=w&1 (4 cols),
// K-half kh=w>>1. Lane owns 16 d at d0=512kh+16lane; weights for 4 cols
// held as u64 pairs in regs. State staged to XOR-swizzled smem.
// Partials -> swizzled pr[64 out][64 src]; 64 threads reduce + epilogue.
// ---------------------------------------------------------------------------
__global__ __launch_bounds__(128, 1) void phase2_scan(
    const float* __restrict__ Ws, const float* __restrict__ bs,
    float* __restrict__ out)
{
    __shared__ float4 st4[2048];     // 32 KB state, f4-swizzled
    __shared__ float  pr[4096];      // 16 KB partials, f4-swizzled

    const int tid  = threadIdx.x;
    const int lane = tid & 31;
    const int w    = tid >> 5;
    const int cg   = w & 1;
    const int kh   = w >> 1;
    const int blk  = blockIdx.x;
    const int d0   = 512 * kh + 16 * lane;
    const int src  = kh * 32 + lane;          // 0..63

    u64 Wn[4][8];
    #pragma unroll
    for (int c = 0; c < 4; ++c) {
        const ulonglong2* wp =
            (const ulonglong2*)&Ws[(size_t)(blk * 8 + 4 * cg + c) * D_SZ + d0];
        #pragma unroll
        for (int q = 0; q < 4; ++q) {
            ulonglong2 v = wp[q];
            Wn[c][2 * q] = v.x; Wn[c][2 * q + 1] = v.y;
        }
    }

    const int ecol = blk * 8 + (tid >> 3);    // tid<64: output column
    const int eb   = tid & 7;                 // batch
    const float bsv = (tid < 64) ? bs[ecol] : 0.0f;
    const int sf   = eb * D_SZ + ecol;        // state float index
    const int sfp  = ((sf >> 2) ^ (((sf >> 2) >> 3) & 7)) * 4 + (sf & 3);

    for (int t = 0; t < S_LEN; ++t) {
        const float4* cur = (const float4*)g_state[t & 1];

        float gv = 0.0f, pv = 0.0f;
        if (tid < 64) {
            size_t gi = ((size_t)eb * S_LEN + t) * D_SZ + ecol;
            gv = g_gate[gi];
            pv = g_proj[gi];
        }

        // stage full state (swizzled)
        #pragma unroll
        for (int ii = 0; ii < 16; ++ii) {
            int i = tid + 128 * ii;
            st4[i ^ ((i >> 3) & 7)] = cur[i];
        }
        __syncthreads();

        // per-batch partial dots, 4 cols per warp, packed pairs
        #pragma unroll
        for (int b = 0; b < 8; ++b) {
            u64 ac[4] = {0ull, 0ull, 0ull, 0ull};
            #pragma unroll
            for (int q = 0; q < 4; ++q) {
                int a = b * 256 + 128 * kh + 4 * lane + q;
                ulonglong2 sv = *(const ulonglong2*)&st4[a ^ ((a >> 3) & 7)];
                #pragma unroll
                for (int c = 0; c < 4; ++c) {
                    ac[c] = ffma2(Wn[c][2 * q],     sv.x, ac[c]);
                    ac[c] = ffma2(Wn[c][2 * q + 1], sv.y, ac[c]);
                }
            }
            #pragma unroll
            for (int c = 0; c < 4; ++c) {
                float2 f = u2f(ac[c]);
                int o = (4 * cg + c) * 8 + b;
                int a = o * 16 + (src >> 2);
                int phys = a ^ ((a >> 4) & 7);
                pr[phys * 4 + (src & 3)] = f.x + f.y;
            }
        }
        __syncthreads();

        // reduce 64 partials per output + gated epilogue (threads 0..63)
        if (tid < 64) {
            float sum = 0.0f;
            #pragma unroll
            for (int q = 0; q < 16; ++q) {
                int a = tid * 16 + q;
                float4 v = ((const float4*)pr)[a ^ ((a >> 4) & 7)];
                sum += (v.x + v.y) + (v.z + v.w);
            }
            float mix  = sum + bsv + pv;
            float sold = ((const float*)st4)[sfp];
            float nxt  = gv * mix + (1.0f - gv) * sold;
            out[((size_t)eb * S_LEN + t) * D_SZ + ecol] = nxt;
            g_state[(t + 1) & 1][sf] = nxt;
        }

        grid_barrier((unsigned)(t + 1));
    }
}

// ---------------------------------------------------------------------------
extern "C" void kernel_launch(void* const* d_in, const int* in_sizes, int n_in,
                              void* d_out, int out_size) {
    const float* x    = (const float*)d_in[0];
    const float* W_in = (const float*)d_in[1];
    const float* b_in = (const float*)d_in[2];
    const float* W_s  = (const float*)d_in[3];
    const float* b_s  = (const float*)d_in[4];
    float* out = (float*)d_out;

    dim3 g1(16, 256);
    phase1_gemm<<<g1, 256>>>(x, W_in, b_in);
    phase2_scan<<<P2_CTAS, 128>>>(W_s, b_s, out);
}

// round 4
// speedup vs baseline: 1.2768x; 1.2027x over previous
#include <cuda_runtime.h>
#include <cstdint>
#include <cstddef>

#define S_LEN 4096
#define B_SZ  8
#define D_SZ  1024
#define M_TOT (B_SZ * S_LEN)

__device__ float g_gate[(size_t)M_TOT * D_SZ];
__device__ float g_proj[(size_t)M_TOT * D_SZ];
__device__ float g_state[2][B_SZ * D_SZ];
__device__ unsigned g_cnt[2];

typedef unsigned long long u64;

__device__ __forceinline__ u64 ffma2(u64 a, u64 b, u64 c) {
    u64 d;
    asm("fma.rn.f32x2 %0, %1, %2, %3;" : "=l"(d) : "l"(a), "l"(b), "l"(c));
    return d;
}
__device__ __forceinline__ u64 packdup(float x) {
    u64 r;
    asm("mov.b64 %0, {%1, %1};" : "=l"(r) : "f"(x));
    return r;
}
__device__ __forceinline__ float2 u2f(u64 v) {
    float2 f;
    asm("mov.b64 {%0, %1}, %2;" : "=f"(f.x), "=f"(f.y) : "l"(v));
    return f;
}

// ---------------------------------------------------------------------------
// Phase 1: z = X@Win^T + bin; gate=sigmoid(z[:,:D]); proj=z[:,D:]
// 128x128x8 tile, 256 thr, 8x8 microtile via packed f32x2. (validated R3)
// CTA(0,0) also zeroes recurrence state + counters.
// ---------------------------------------------------------------------------
__global__ __launch_bounds__(256, 2) void phase1_gemm(
    const float* __restrict__ X, const float* __restrict__ Win,
    const float* __restrict__ bin)
{
    __shared__ float As[8][128];
    __shared__ float Bs[8][128];

    const int tid = threadIdx.x;
    const int tx = tid & 15, ty = tid >> 4;
    const int m0 = blockIdx.y * 128, n0 = blockIdx.x * 128;

    if (blockIdx.x == 0 && blockIdx.y == 0) {
        if (tid == 0) { g_cnt[0] = 0u; g_cnt[1] = 0u; }
        for (int i = tid; i < B_SZ * D_SZ; i += 256) g_state[0][i] = 0.0f;
    }

    const int lm = tid >> 1;
    const int lk = (tid & 1) * 4;

    u64 acc[8][4];
    #pragma unroll
    for (int i = 0; i < 8; ++i)
        #pragma unroll
        for (int p = 0; p < 4; ++p) acc[i][p] = 0ull;

    const float* Aptr = X   + (size_t)(m0 + lm) * D_SZ + lk;
    const float* Bptr = Win + (size_t)(n0 + lm) * D_SZ + lk;

    for (int k0 = 0; k0 < D_SZ; k0 += 8) {
        float4 a = *(const float4*)(Aptr + k0);
        float4 b = *(const float4*)(Bptr + k0);
        As[lk + 0][lm] = a.x; As[lk + 1][lm] = a.y;
        As[lk + 2][lm] = a.z; As[lk + 3][lm] = a.w;
        Bs[lk + 0][lm] = b.x; Bs[lk + 1][lm] = b.y;
        Bs[lk + 2][lm] = b.z; Bs[lk + 3][lm] = b.w;
        __syncthreads();

        #pragma unroll
        for (int k = 0; k < 8; ++k) {
            float4 a0 = *(const float4*)&As[k][ty * 8];
            float4 a1 = *(const float4*)&As[k][ty * 8 + 4];
            u64 Ad[8] = {packdup(a0.x), packdup(a0.y), packdup(a0.z), packdup(a0.w),
                         packdup(a1.x), packdup(a1.y), packdup(a1.z), packdup(a1.w)};
            ulonglong2 b01 = *(const ulonglong2*)&Bs[k][tx * 8];
            ulonglong2 b23 = *(const ulonglong2*)&Bs[k][tx * 8 + 4];
            u64 Bp[4] = {b01.x, b01.y, b23.x, b23.y};
            #pragma unroll
            for (int i = 0; i < 8; ++i)
                #pragma unroll
                for (int p = 0; p < 4; ++p)
                    acc[i][p] = ffma2(Ad[i], Bp[p], acc[i][p]);
        }
        __syncthreads();
    }

    const bool is_gate = (n0 < D_SZ);
    #pragma unroll
    for (int i = 0; i < 8; ++i) {
        const int m = m0 + ty * 8 + i;
        #pragma unroll
        for (int p = 0; p < 4; ++p) {
            float2 f = u2f(acc[i][p]);
            const int n = n0 + tx * 8 + 2 * p;
            float v0 = f.x + bin[n];
            float v1 = f.y + bin[n + 1];
            if (is_gate) {
                g_gate[(size_t)m * D_SZ + n]     = 1.0f / (1.0f + __expf(-v0));
                g_gate[(size_t)m * D_SZ + n + 1] = 1.0f / (1.0f + __expf(-v1));
            } else {
                g_proj[(size_t)m * D_SZ + n - D_SZ]     = v0;
                g_proj[(size_t)m * D_SZ + n - D_SZ + 1] = v1;
            }
        }
    }
}

// ---------------------------------------------------------------------------
// Phase 2: 4096-step recurrence, batch-split.
// 128 CTAs x 256 thr. Group grp = blk>>6 owns batches [4grp, 4grp+4);
// chunk = blk&63 owns cols [16*chunk, +16). Two independent 64-CTA sync
// groups with their own counter.
// Warp w (0..7): col-group cg=w&3 (4 cols), K-half kh=w>>2. Lane owns 16 d.
// Weights in regs (32 u64/lane). State (16KB) staged to swizzled smem via
// __ldcg. Partials -> swizzled pr[64][64]; 64 threads reduce + epilogue.
// ---------------------------------------------------------------------------
__global__ __launch_bounds__(256, 1) void phase2_scan(
    const float* __restrict__ Ws, const float* __restrict__ bs,
    float* __restrict__ out)
{
    __shared__ float4 st4[1024];     // 16 KB: 4 batches x 1024 cols, swizzled
    __shared__ float  pr[4096];      // 16 KB: partials [64 out][64 src], swizzled

    const int tid   = threadIdx.x;
    const int lane  = tid & 31;
    const int w     = tid >> 5;
    const int cg    = w & 3;
    const int kh    = w >> 2;
    const int blk   = blockIdx.x;
    const int grp   = blk >> 6;          // 0 or 1: batches 4grp..4grp+3
    const int chunk = blk & 63;          // cols 16*chunk..+16
    const int d0    = 512 * kh + 16 * lane;

    // Weights: Wn[c][2q+h] = pair (Ws[e][d0+4q+2h], ...+1), e=16chunk+4cg+c
    u64 Wn[4][8];
    #pragma unroll
    for (int c = 0; c < 4; ++c) {
        const ulonglong2* wp =
            (const ulonglong2*)&Ws[(size_t)(chunk * 16 + 4 * cg + c) * D_SZ + d0];
        #pragma unroll
        for (int q = 0; q < 4; ++q) {
            ulonglong2 v = wp[q];
            Wn[c][2 * q] = v.x; Wn[c][2 * q + 1] = v.y;
        }
    }

    // epilogue assignment (tid < 64): o = t -> cidx = t>>2, bl = t&3
    const int cidx = tid >> 2;
    const int bl   = tid & 3;
    const int ecol = chunk * 16 + cidx;
    const int eb   = 4 * grp + bl;
    const float bsv = (tid < 64) ? bs[ecol] : 0.0f;
    const int sf   = bl * D_SZ + ecol;   // smem float index of old state
    const int sfp  = (((sf >> 2) ^ (((sf >> 2) >> 3) & 7)) << 2) | (sf & 3);

    const int base4 = 256 * 0 + 128 * kh + 4 * lane;  // within-batch f4 base
    const int src   = kh * 32 + lane;                 // 0..63
    volatile unsigned* cnt = (volatile unsigned*)&g_cnt[grp];

    for (int t = 0; t < S_LEN; ++t) {
        // prefetch gate/proj (independent of state; hides DRAM latency)
        float gv = 0.0f, pv = 0.0f;
        if (tid < 64) {
            size_t gi = ((size_t)eb * S_LEN + t) * D_SZ + ecol;
            gv = __ldcg(&g_gate[gi]);
            pv = __ldcg(&g_proj[gi]);
        }

        // wait for all 64 CTAs of this group to have produced state t
        if (tid == 0) {
            unsigned target = (unsigned)(64 * t);
            while (*cnt < target) __nanosleep(20);
            __threadfence();
        }
        __syncthreads();

        // stage this group's 4-batch state slice (16KB) via L2, swizzled
        const float4* cur = (const float4*)&g_state[t & 1][grp * 4 * D_SZ];
        #pragma unroll
        for (int ii = 0; ii < 4; ++ii) {
            int i = tid + 256 * ii;
            st4[i ^ ((i >> 3) & 7)] = __ldcg(&cur[i]);
        }
        __syncthreads();

        // partial dots: acc[bl][c] packed pairs over lane's 16 d
        u64 ac[4][4];
        #pragma unroll
        for (int b = 0; b < 4; ++b)
            #pragma unroll
            for (int c = 0; c < 4; ++c) ac[b][c] = 0ull;

        #pragma unroll
        for (int b = 0; b < 4; ++b) {
            #pragma unroll
            for (int q = 0; q < 4; ++q) {
                int a = b * 256 + base4 + q;
                ulonglong2 sv = *(const ulonglong2*)&st4[a ^ ((a >> 3) & 7)];
                #pragma unroll
                for (int c = 0; c < 4; ++c) {
                    ac[b][c] = ffma2(Wn[c][2 * q],     sv.x, ac[b][c]);
                    ac[b][c] = ffma2(Wn[c][2 * q + 1], sv.y, ac[b][c]);
                }
            }
        }

        // write partials: output o = (4cg+c)*4 + b, source src
        #pragma unroll
        for (int b = 0; b < 4; ++b) {
            #pragma unroll
            for (int c = 0; c < 4; ++c) {
                float2 f = u2f(ac[b][c]);
                int o = ((4 * cg + c) << 2) | b;
                int a = o * 16 + (src >> 2);
                pr[((a ^ ((a >> 4) & 7)) << 2) | (src & 3)] = f.x + f.y;
            }
        }
        __syncthreads();

        // reduce 64 partials per output + gated epilogue (threads 0..63)
        if (tid < 64) {
            float sum = 0.0f;
            #pragma unroll
            for (int q = 0; q < 16; ++q) {
                int a = tid * 16 + q;
                float4 v = ((const float4*)pr)[a ^ ((a >> 4) & 7)];
                sum += (v.x + v.y) + (v.z + v.w);
            }
            float mix  = sum + bsv + pv;
            float sold = ((const float*)st4)[sfp];
            float nxt  = gv * mix + (1.0f - gv) * sold;
            out[((size_t)eb * S_LEN + t) * D_SZ + ecol] = nxt;
            g_state[(t + 1) & 1][eb * D_SZ + ecol] = nxt;
        }
        __syncthreads();

        // arrive: state t+1 from this CTA is published
        if (tid == 0) {
            __threadfence();
            atomicAdd(&g_cnt[grp], 1u);
        }
    }
}

// ---------------------------------------------------------------------------
extern "C" void kernel_launch(void* const* d_in, const int* in_sizes, int n_in,
                              void* d_out, int out_size) {
    const float* x    = (const float*)d_in[0];
    const float* W_in = (const float*)d_in[1];
    const float* b_in = (const float*)d_in[2];
    const float* W_s  = (const float*)d_in[3];
    const float* b_s  = (const float*)d_in[4];
    float* out = (float*)d_out;

    dim3 g1(16, 256);
    phase1_gemm<<<g1, 256>>>(x, W_in, b_in);
    phase2_scan<<<128, 256>>>(W_s, b_s, out);
}